// round 2
// baseline (speedup 1.0000x reference)
#include <cuda_runtime.h>
#include <cstdint>

// Problem constants (fixed by setup_inputs: N=32768, D=512, F=64)
#define D_DIM 512
#define F_DIM 64
#define BN    32     // rows per CTA in main kernel
#define TNR   2      // rows per thread
#define KT    32     // k-chunk of M staged in smem
#define NTH   128    // threads in main kernel = (BN/TNR)*8

// Scratch (device globals: allocation-free rule)
__device__ float g_M[D_DIM * F_DIM];  // M[d][f] = V1[f][d] + sum_e W[f][d][e]*x2[e]
__device__ float g_c[F_DIM];          // c[f] = V2[f]·x2 + b[f]

// ---------------------------------------------------------------------------
// helpers
// ---------------------------------------------------------------------------
__device__ __forceinline__ unsigned smem_u32(const void* p) {
    return (unsigned)__cvta_generic_to_shared(p);
}
__device__ __forceinline__ void cp_async16(unsigned saddr, const void* g) {
    asm volatile("cp.async.cg.shared.global [%0], [%1], 16;\n" :: "r"(saddr), "l"(g));
}
#define CP_COMMIT() asm volatile("cp.async.commit_group;\n")
#define CP_WAIT(n)  asm volatile("cp.async.wait_group %0;\n" :: "n"(n))

// Packed fp32x2 FMA (sm_100+): d = a*b + d  (elementwise on 2 floats)
__device__ __forceinline__ void ffma2(float2& d, const float2& a, const float2& b) {
    asm("fma.rn.f32x2 %0, %1, %2, %0;"
        : "+l"(reinterpret_cast<unsigned long long&>(d))
        : "l"(reinterpret_cast<const unsigned long long&>(a)),
          "l"(reinterpret_cast<const unsigned long long&>(b)));
}

// ---------------------------------------------------------------------------
// Kernel A: stream W once -> build M[d][f]; also c[f]
// Each warp handles 2 consecutive (f,d) rows -> 8 independent LDG.128 in
// flight per lane (MLP=8) before any dependent math.
// grid: 2048 blocks for M (8 warps x 2 rows x 16 rows/block) + 1 block for c
// ---------------------------------------------------------------------------
__global__ void __launch_bounds__(256) prep_kernel(
    const float* __restrict__ x2, const float* __restrict__ V,
    const float* __restrict__ W, const float* __restrict__ b)
{
    __shared__ float s_x2[D_DIM];
    int tid = threadIdx.x;
    for (int i = tid; i < D_DIM; i += blockDim.x) s_x2[i] = x2[i];
    __syncthreads();

    int lane = tid & 31;
    int warp = tid >> 5;
    const float4* x2v = reinterpret_cast<const float4*>(s_x2);

    if (blockIdx.x < 2048) {
        int r0 = blockIdx.x * 16 + warp * 2;   // rows r0, r0+1 of 32768
        const float4* w0 = reinterpret_cast<const float4*>(W + (size_t)r0 * D_DIM);
        const float4* w1 = reinterpret_cast<const float4*>(W + (size_t)(r0 + 1) * D_DIM);

        // issue all 8 loads up-front (independent -> MLP 8)
        float4 wv0[4], wv1[4];
        #pragma unroll
        for (int it = 0; it < 4; it++) wv0[it] = w0[lane + it * 32];
        #pragma unroll
        for (int it = 0; it < 4; it++) wv1[it] = w1[lane + it * 32];

        float a0 = 0.f, a1 = 0.f;
        #pragma unroll
        for (int it = 0; it < 4; it++) {
            float4 xv = x2v[lane + it * 32];
            a0 += wv0[it].x * xv.x + wv0[it].y * xv.y + wv0[it].z * xv.z + wv0[it].w * xv.w;
            a1 += wv1[it].x * xv.x + wv1[it].y * xv.y + wv1[it].z * xv.z + wv1[it].w * xv.w;
        }
        #pragma unroll
        for (int o = 16; o; o >>= 1) {
            a0 += __shfl_xor_sync(0xffffffffu, a0, o);
            a1 += __shfl_xor_sync(0xffffffffu, a1, o);
        }
        if (lane == 0) {
            int f0 = r0 >> 9, d0 = r0 & 511;
            int r1 = r0 + 1;
            int f1 = r1 >> 9, d1 = r1 & 511;
            g_M[d0 * F_DIM + f0] = a0 + V[(size_t)f0 * (2 * D_DIM) + d0];
            g_M[d1 * F_DIM + f1] = a1 + V[(size_t)f1 * (2 * D_DIM) + d1];
        }
    } else {
        // c[f] = V2[f]·x2 + b[f] ; 8 warps x 8 f each
        #pragma unroll
        for (int j = 0; j < 8; j++) {
            int f = warp + j * 8;
            const float4* vrow =
                reinterpret_cast<const float4*>(V + (size_t)f * (2 * D_DIM) + D_DIM);
            float acc = 0.f;
            #pragma unroll
            for (int it = 0; it < 4; it++) {
                float4 vv = vrow[lane + it * 32];
                float4 xv = x2v[lane + it * 32];
                acc += vv.x * xv.x + vv.y * xv.y + vv.z * xv.z + vv.w * xv.w;
            }
            #pragma unroll
            for (int o = 16; o; o >>= 1) acc += __shfl_xor_sync(0xffffffffu, acc, o);
            if (lane == 0) g_c[f] = acc + b[f];
        }
    }
}

// ---------------------------------------------------------------------------
// Kernel B: fm = x1 @ M (+c), then L1-normalize/relu/@U, fused.
// CTA: 32 rows x 64 f, 128 threads, 7 CTAs/SM target (16KB smem, <=73 regs).
// Thread: 2 rows x 8 f (4 float2 accumulators per row).
// M chunks (32 k x 64 f = 8KB) double-buffered via cp.async.
// x1 a-frags direct from global (8-lane dup merges to 1 sector), prefetch 1.
// ---------------------------------------------------------------------------
__global__ void __launch_bounds__(NTH, 7) main_kernel(
    const float* __restrict__ x1, const float* __restrict__ U,
    float* __restrict__ out)
{
    __shared__ float sM[2][KT][F_DIM];   // 16 KB
    __shared__ float sU[F_DIM];
    __shared__ float sc[F_DIM];

    int tid = threadIdx.x;
    if (tid < F_DIM) { sU[tid] = U[tid]; sc[tid] = g_c[tid]; }

    int fc = tid & 7;    // f-group 0..7  -> f = fc*8 .. fc*8+7
    int nr = tid >> 3;   // row-group 0..15 -> rows nr, nr+16
    int base = blockIdx.x * BN;
    const float* x1b = x1 + (size_t)base * D_DIM;

    // chunk loader: 8KB = 512 float4, 4 per thread, lanes contiguous
    auto load_chunk = [&](int kt, int bi) {
        const float4* src = reinterpret_cast<const float4*>(g_M + kt * KT * F_DIM);
        unsigned sbase = smem_u32(&sM[bi][0][0]);
        #pragma unroll
        for (int j = 0; j < 4; j++) {
            int idx = j * NTH + tid;
            cp_async16(sbase + idx * 16, src + idx);
        }
    };

    load_chunk(0, 0);
    CP_COMMIT();

    // prefetch a-frags for global k4 = 0
    float4 a_nxt[TNR];
    #pragma unroll
    for (int i = 0; i < TNR; i++)
        a_nxt[i] = *reinterpret_cast<const float4*>(x1b + (size_t)(nr + 16 * i) * D_DIM);

    float2 acc[TNR][4];
    #pragma unroll
    for (int i = 0; i < TNR; i++)
        #pragma unroll
        for (int p = 0; p < 4; p++) acc[i][p] = make_float2(0.f, 0.f);

    int buf = 0;
    for (int kt = 0; kt < D_DIM / KT; kt++) {   // 16 chunks
        if (kt < D_DIM / KT - 1) {
            load_chunk(kt + 1, buf ^ 1);
            CP_COMMIT();
            CP_WAIT(1);
        } else {
            CP_WAIT(0);
        }
        __syncthreads();

        #pragma unroll
        for (int k4 = 0; k4 < KT / 4; k4++) {   // 8
            float4 a_cur[TNR];
            #pragma unroll
            for (int i = 0; i < TNR; i++) a_cur[i] = a_nxt[i];

            int gk4 = kt * (KT / 4) + k4 + 1;
            if (gk4 < D_DIM / 4) {
                #pragma unroll
                for (int i = 0; i < TNR; i++)
                    a_nxt[i] = *reinterpret_cast<const float4*>(
                        x1b + (size_t)(nr + 16 * i) * D_DIM + gk4 * 4);
            }

            #pragma unroll
            for (int j = 0; j < 4; j++) {
                int k = k4 * 4 + j;
                float4 b0 = *reinterpret_cast<const float4*>(&sM[buf][k][fc * 8]);
                float4 b1 = *reinterpret_cast<const float4*>(&sM[buf][k][fc * 8 + 4]);
                float2 bp[4] = { make_float2(b0.x, b0.y), make_float2(b0.z, b0.w),
                                 make_float2(b1.x, b1.y), make_float2(b1.z, b1.w) };
                #pragma unroll
                for (int i = 0; i < TNR; i++) {
                    float a = (j == 0) ? a_cur[i].x : (j == 1) ? a_cur[i].y
                              : (j == 2) ? a_cur[i].z : a_cur[i].w;
                    float2 av = make_float2(a, a);
                    #pragma unroll
                    for (int p = 0; p < 4; p++) ffma2(acc[i][p], av, bp[p]);
                }
            }
        }
        __syncthreads();
        buf ^= 1;
    }

    // Epilogue: per-row |fm| sum and relu(fm)*U sum, reduced over the 8 fc lanes
    #pragma unroll
    for (int i = 0; i < TNR; i++) {
        float s = 0.f, num = 0.f;
        #pragma unroll
        for (int p = 0; p < 4; p++) {
            int f = fc * 8 + 2 * p;
            float fx = acc[i][p].x + sc[f];
            float fy = acc[i][p].y + sc[f + 1];
            s   += fabsf(fx) + fabsf(fy);
            num += fmaxf(fx, 0.f) * sU[f] + fmaxf(fy, 0.f) * sU[f + 1];
        }
        #pragma unroll
        for (int o = 1; o < 8; o <<= 1) {
            s   += __shfl_xor_sync(0xffffffffu, s, o);
            num += __shfl_xor_sync(0xffffffffu, num, o);
        }
        if (fc == 0) {
            float denom = fmaxf(s, 1e-12f);
            out[base + nr + 16 * i] = num / denom;
        }
    }
}

// ---------------------------------------------------------------------------
// launch
// ---------------------------------------------------------------------------
extern "C" void kernel_launch(void* const* d_in, const int* in_sizes, int n_in,
                              void* d_out, int out_size)
{
    const float* x1 = (const float*)d_in[0];   // (N, 512)
    const float* x2 = (const float*)d_in[1];   // (1, 512)
    const float* V  = (const float*)d_in[2];   // (64, 1024)
    const float* W  = (const float*)d_in[3];   // (64, 512, 512)
    const float* b  = (const float*)d_in[4];   // (64,)
    const float* U  = (const float*)d_in[5];   // (64, 1)
    float* out = (float*)d_out;                // (N, 1)

    int N = in_sizes[0] / D_DIM;               // 32768

    prep_kernel<<<2048 + 1, 256>>>(x2, V, W, b);
    main_kernel<<<N / BN, NTH>>>(x1, U, out);
}

// round 3
// speedup vs baseline: 1.3948x; 1.3948x over previous
#include <cuda_runtime.h>
#include <cstdint>

// Problem constants (fixed by setup_inputs: N=32768, D=512, F=64)
#define D_DIM 512
#define F_DIM 64
#define TILE  256    // rows per CTA (one tile per CTA, grid = 128)
#define TNR   4      // rows per thread
#define NTH   512    // threads in main kernel
#define NK4   (D_DIM / 4)   // 128

// Scratch (device globals: allocation-free rule)
__device__ float g_M[D_DIM * F_DIM];  // M[d][f] = V1[f][d] + sum_e W[f][d][e]*x2[e]
__device__ float g_c[F_DIM];          // c[f] = V2[f]·x2 + b[f]

// ---------------------------------------------------------------------------
// helpers
// ---------------------------------------------------------------------------
__device__ __forceinline__ unsigned smem_u32(const void* p) {
    return (unsigned)__cvta_generic_to_shared(p);
}
__device__ __forceinline__ void cp_async16(unsigned saddr, const void* g) {
    asm volatile("cp.async.cg.shared.global [%0], [%1], 16;\n" :: "r"(saddr), "l"(g));
}
#define CP_COMMIT() asm volatile("cp.async.commit_group;\n")
#define CP_WAIT(n)  asm volatile("cp.async.wait_group %0;\n" :: "n"(n))

// Packed fp32x2 FMA (sm_100+): d = a*b + d  (elementwise on 2 floats)
__device__ __forceinline__ void ffma2(float2& d, const float2& a, const float2& b) {
    asm("fma.rn.f32x2 %0, %1, %2, %0;"
        : "+l"(reinterpret_cast<unsigned long long&>(d))
        : "l"(reinterpret_cast<const unsigned long long&>(a)),
          "l"(reinterpret_cast<const unsigned long long&>(b)));
}

// ---------------------------------------------------------------------------
// Kernel A: stream W once -> build M[d][f]; also c[f]
// Each warp handles 4 consecutive (f,d) rows -> 16 independent LDG.128 in
// flight per lane (MLP=16). 1024 blocks x 32 rows + 1 block for c.
// ---------------------------------------------------------------------------
__global__ void __launch_bounds__(256) prep_kernel(
    const float* __restrict__ x2, const float* __restrict__ V,
    const float* __restrict__ W, const float* __restrict__ b)
{
    __shared__ float s_x2[D_DIM];
    int tid = threadIdx.x;
    for (int i = tid; i < D_DIM; i += blockDim.x) s_x2[i] = x2[i];
    __syncthreads();

    int lane = tid & 31;
    int warp = tid >> 5;
    const float4* x2v = reinterpret_cast<const float4*>(s_x2);

    if (blockIdx.x < 1024) {
        int r0 = blockIdx.x * 32 + warp * 4;   // rows r0..r0+3 of 32768

        float4 wv[4][4];
        #pragma unroll
        for (int r = 0; r < 4; r++) {
            const float4* wr =
                reinterpret_cast<const float4*>(W + (size_t)(r0 + r) * D_DIM);
            #pragma unroll
            for (int it = 0; it < 4; it++) wv[r][it] = wr[lane + it * 32];
        }

        float a[4] = {0.f, 0.f, 0.f, 0.f};
        #pragma unroll
        for (int it = 0; it < 4; it++) {
            float4 xv = x2v[lane + it * 32];
            #pragma unroll
            for (int r = 0; r < 4; r++) {
                a[r] += wv[r][it].x * xv.x + wv[r][it].y * xv.y
                      + wv[r][it].z * xv.z + wv[r][it].w * xv.w;
            }
        }
        #pragma unroll
        for (int o = 16; o; o >>= 1) {
            #pragma unroll
            for (int r = 0; r < 4; r++)
                a[r] += __shfl_xor_sync(0xffffffffu, a[r], o);
        }
        if (lane < 4) {
            int r = r0 + lane;
            int f = r >> 9, d = r & 511;
            float av = __shfl_sync(0xffffffffu, a[lane], 0);  // lane r's acc is in lane0 of a[r]
            // simpler: recompute via shfl of each a[r] — do it directly:
            // (av computed below)
            (void)av;
        }
        if (lane == 0) {
            #pragma unroll
            for (int r = 0; r < 4; r++) {
                int rr = r0 + r;
                int f = rr >> 9, d = rr & 511;
                g_M[d * F_DIM + f] = a[r] + V[(size_t)f * (2 * D_DIM) + d];
            }
        }
    } else {
        // c[f] = V2[f]·x2 + b[f] ; 8 warps x 8 f each
        #pragma unroll
        for (int j = 0; j < 8; j++) {
            int f = warp + j * 8;
            const float4* vrow =
                reinterpret_cast<const float4*>(V + (size_t)f * (2 * D_DIM) + D_DIM);
            float acc = 0.f;
            #pragma unroll
            for (int it = 0; it < 4; it++) {
                float4 vv = vrow[lane + it * 32];
                float4 xv = x2v[lane + it * 32];
                acc += vv.x * xv.x + vv.y * xv.y + vv.z * xv.z + vv.w * xv.w;
            }
            #pragma unroll
            for (int o = 16; o; o >>= 1) acc += __shfl_xor_sync(0xffffffffu, acc, o);
            if (lane == 0) g_c[f] = acc + b[f];
        }
    }
}

// ---------------------------------------------------------------------------
// Kernel B (persistent M): the ENTIRE 128KB M lives in dynamic smem, loaded
// once per CTA. Grid = 128 CTAs x 512 threads, one 256-row tile per CTA.
// Thread: 4 rows x 8 f. Inner loop is sync-free: LDG x1 (depth-2 prefetch),
// LDS M (conflict-free), FFMA2. Fused L1-norm/relu/@U epilogue.
// ---------------------------------------------------------------------------
__global__ void __launch_bounds__(NTH, 1) main_kernel(
    const float* __restrict__ x1, const float* __restrict__ U,
    float* __restrict__ out)
{
    extern __shared__ float smem[];
    float* sM = smem;                 // [512][64] = 128 KB
    float* sU = smem + D_DIM * F_DIM; // 64
    float* sc = sU + F_DIM;           // 64

    int tid = threadIdx.x;

    // prologue: load all of M via cp.async (8192 x 16B, 16 per thread)
    {
        const float4* src = reinterpret_cast<const float4*>(g_M);
        unsigned sbase = smem_u32(sM);
        #pragma unroll
        for (int j = 0; j < 16; j++) {
            int idx = j * NTH + tid;
            cp_async16(sbase + idx * 16, src + idx);
        }
        CP_COMMIT();
    }
    if (tid < F_DIM) { sU[tid] = U[tid]; sc[tid] = g_c[tid]; }
    CP_WAIT(0);
    __syncthreads();

    int fc = tid & 7;    // f-group 0..7 -> f = fc*8 .. fc*8+7
    int nr = tid >> 3;   // row-group 0..63 -> rows nr + 64*i
    int base = blockIdx.x * TILE;
    const float* x1b = x1 + (size_t)base * D_DIM;

    const float* rowp[TNR];
    #pragma unroll
    for (int i = 0; i < TNR; i++) rowp[i] = x1b + (size_t)(nr + 64 * i) * D_DIM;

    // depth-2 prefetch pipeline for a-frags
    float4 a0[TNR], a1[TNR];
    #pragma unroll
    for (int i = 0; i < TNR; i++) a0[i] = *reinterpret_cast<const float4*>(rowp[i]);
    #pragma unroll
    for (int i = 0; i < TNR; i++) a1[i] = *reinterpret_cast<const float4*>(rowp[i] + 4);

    float2 acc[TNR][4];
    #pragma unroll
    for (int i = 0; i < TNR; i++)
        #pragma unroll
        for (int p = 0; p < 4; p++) acc[i][p] = make_float2(0.f, 0.f);

    for (int k4 = 0; k4 < NK4; k4++) {
        float4 ac[TNR];
        #pragma unroll
        for (int i = 0; i < TNR; i++) { ac[i] = a0[i]; a0[i] = a1[i]; }

        if (k4 + 2 < NK4) {
            #pragma unroll
            for (int i = 0; i < TNR; i++)
                a1[i] = *reinterpret_cast<const float4*>(rowp[i] + (k4 + 2) * 4);
        }

        #pragma unroll
        for (int j = 0; j < 4; j++) {
            int k = k4 * 4 + j;
            float4 b0 = *reinterpret_cast<const float4*>(&sM[k * F_DIM + fc * 8]);
            float4 b1 = *reinterpret_cast<const float4*>(&sM[k * F_DIM + fc * 8 + 4]);
            float2 bp[4] = { make_float2(b0.x, b0.y), make_float2(b0.z, b0.w),
                             make_float2(b1.x, b1.y), make_float2(b1.z, b1.w) };
            #pragma unroll
            for (int i = 0; i < TNR; i++) {
                float a = (j == 0) ? ac[i].x : (j == 1) ? ac[i].y
                          : (j == 2) ? ac[i].z : ac[i].w;
                float2 av = make_float2(a, a);
                #pragma unroll
                for (int p = 0; p < 4; p++) ffma2(acc[i][p], av, bp[p]);
            }
        }
    }

    // Epilogue: per-row |fm| sum and relu(fm)*U sum, reduced over the 8 fc lanes
    #pragma unroll
    for (int i = 0; i < TNR; i++) {
        float s = 0.f, num = 0.f;
        #pragma unroll
        for (int p = 0; p < 4; p++) {
            int f = fc * 8 + 2 * p;
            float fx = acc[i][p].x + sc[f];
            float fy = acc[i][p].y + sc[f + 1];
            s   += fabsf(fx) + fabsf(fy);
            num += fmaxf(fx, 0.f) * sU[f] + fmaxf(fy, 0.f) * sU[f + 1];
        }
        #pragma unroll
        for (int o = 1; o < 8; o <<= 1) {
            s   += __shfl_xor_sync(0xffffffffu, s, o);
            num += __shfl_xor_sync(0xffffffffu, num, o);
        }
        if (fc == 0) {
            float denom = fmaxf(s, 1e-12f);
            out[base + nr + 64 * i] = num / denom;
        }
    }
}

// ---------------------------------------------------------------------------
// launch
// ---------------------------------------------------------------------------
extern "C" void kernel_launch(void* const* d_in, const int* in_sizes, int n_in,
                              void* d_out, int out_size)
{
    const float* x1 = (const float*)d_in[0];   // (N, 512)
    const float* x2 = (const float*)d_in[1];   // (1, 512)
    const float* V  = (const float*)d_in[2];   // (64, 1024)
    const float* W  = (const float*)d_in[3];   // (64, 512, 512)
    const float* b  = (const float*)d_in[4];   // (64,)
    const float* U  = (const float*)d_in[5];   // (64, 1)
    float* out = (float*)d_out;                // (N, 1)

    int N = in_sizes[0] / D_DIM;               // 32768
    int smem_bytes = (D_DIM * F_DIM + 2 * F_DIM) * sizeof(float);  // ~128.5 KB

    static bool attr_set = false;  // idempotent device-state config (no work skipped)
    cudaFuncSetAttribute(main_kernel, cudaFuncAttributeMaxDynamicSharedMemorySize,
                         smem_bytes);
    (void)attr_set;

    prep_kernel<<<1024 + 1, 256>>>(x2, V, W, b);
    main_kernel<<<N / TILE, NTH, smem_bytes>>>(x1, U, out);
}

// round 5
// speedup vs baseline: 3.5856x; 2.5707x over previous
#include <cuda_runtime.h>
#include <cuda_bf16.h>
#include <cstdint>

// Problem constants (fixed by setup_inputs: N=32768, D=512, F=64)
#define D_DIM  512
#define F_DIM  64
#define TILE_M 256          // rows per CTA (16 warps x 16 rows)
#define NTH    512
#define NKS    (D_DIM / 16) // 32 k-steps

// SMEM: B_hi [512k][64f] bf16 swizzled (64KB) | B_lo (64KB) | sc[64] | sU[64]
#define BHI_OFF 0
#define BLO_OFF 65536
#define AUX_OFF 131072
#define SMEM_BYTES (131072 + 512 + 1024)

// Scratch (device globals: allocation-free rule)
__device__ uint16_t g_Mbhi[D_DIM * F_DIM];  // bf16 hi of M[k][f]
__device__ uint16_t g_Mblo[D_DIM * F_DIM];  // bf16 lo
__device__ float    g_c[F_DIM];             // c[f] = V2[f]·x2 + b[f]

// ---------------------------------------------------------------------------
// helpers
// ---------------------------------------------------------------------------
__device__ __forceinline__ unsigned smem_u32(const void* p) {
    return (unsigned)__cvta_generic_to_shared(p);
}
__device__ __forceinline__ void cp_async16(unsigned saddr, const void* g) {
    asm volatile("cp.async.cg.shared.global [%0], [%1], 16;\n" :: "r"(saddr), "l"(g));
}
#define CP_COMMIT() asm volatile("cp.async.commit_group;\n")
#define CP_WAIT0()  asm volatile("cp.async.wait_group 0;\n")

// float2 -> packed bf16x2 hi (RNE) + packed bf16x2 lo (residual)
__device__ __forceinline__ void split2(float2 e, uint32_t& hp, uint32_t& lp) {
    uint32_t u0 = __float_as_uint(e.x), u1 = __float_as_uint(e.y);
    uint32_t r0 = (u0 + 0x7FFFu + ((u0 >> 16) & 1u)) & 0xFFFF0000u;
    uint32_t r1 = (u1 + 0x7FFFu + ((u1 >> 16) & 1u)) & 0xFFFF0000u;
    hp = __byte_perm(r0, r1, 0x7632);           // lo16 = e.x_hi, hi16 = e.y_hi
    float l0 = e.x - __uint_as_float(r0);
    float l1 = e.y - __uint_as_float(r1);
    asm("cvt.rn.bf16x2.f32 %0, %1, %2;" : "=r"(lp) : "f"(l1), "f"(l0));
}

#define LDMX4T(r0, r1, r2, r3, a) \
    asm volatile("ldmatrix.sync.aligned.m8n8.x4.trans.shared.b16 {%0,%1,%2,%3}, [%4];" \
                 : "=r"(r0), "=r"(r1), "=r"(r2), "=r"(r3) : "r"(a))

#define MMA16816(d, a0, a1, a2, a3, b0, b1) \
    asm volatile("mma.sync.aligned.m16n8k16.row.col.f32.bf16.bf16.f32 " \
                 "{%0,%1,%2,%3}, {%4,%5,%6,%7}, {%8,%9}, {%0,%1,%2,%3};" \
                 : "+f"((d)[0]), "+f"((d)[1]), "+f"((d)[2]), "+f"((d)[3]) \
                 : "r"(a0), "r"(a1), "r"(a2), "r"(a3), "r"(b0), "r"(b1))

// ---------------------------------------------------------------------------
// Kernel A: stream W once -> M[k][f] split to bf16 hi/lo in global; also c[f]
// Each warp: 4 consecutive (f,d) rows of W, MLP=16 LDG.128.
// ---------------------------------------------------------------------------
__global__ void __launch_bounds__(256) prep_kernel(
    const float* __restrict__ x2, const float* __restrict__ V,
    const float* __restrict__ W, const float* __restrict__ b)
{
    __shared__ float s_x2[D_DIM];
    int tid = threadIdx.x;
    for (int i = tid; i < D_DIM; i += blockDim.x) s_x2[i] = x2[i];
    __syncthreads();

    int lane = tid & 31;
    int warp = tid >> 5;
    const float4* x2v = reinterpret_cast<const float4*>(s_x2);

    if (blockIdx.x < 1024) {
        int r0 = blockIdx.x * 32 + warp * 4;   // rows r0..r0+3 of 32768

        float4 wv[4][4];
        #pragma unroll
        for (int r = 0; r < 4; r++) {
            const float4* wr =
                reinterpret_cast<const float4*>(W + (size_t)(r0 + r) * D_DIM);
            #pragma unroll
            for (int it = 0; it < 4; it++) wv[r][it] = wr[lane + it * 32];
        }

        float a[4] = {0.f, 0.f, 0.f, 0.f};
        #pragma unroll
        for (int it = 0; it < 4; it++) {
            float4 xv = x2v[lane + it * 32];
            #pragma unroll
            for (int r = 0; r < 4; r++) {
                a[r] += wv[r][it].x * xv.x + wv[r][it].y * xv.y
                      + wv[r][it].z * xv.z + wv[r][it].w * xv.w;
            }
        }
        #pragma unroll
        for (int o = 16; o; o >>= 1) {
            #pragma unroll
            for (int r = 0; r < 4; r++)
                a[r] += __shfl_xor_sync(0xffffffffu, a[r], o);
        }
        if (lane == 0) {
            #pragma unroll
            for (int r = 0; r < 4; r++) {
                int rr = r0 + r;
                int f = rr >> 9, d = rr & 511;
                float v = a[r] + V[(size_t)f * (2 * D_DIM) + d];
                uint32_t u = __float_as_uint(v);
                uint32_t rh = (u + 0x7FFFu + ((u >> 16) & 1u)) & 0xFFFF0000u;
                float lo = v - __uint_as_float(rh);
                uint32_t ul = __float_as_uint(lo);
                uint32_t rl = (ul + 0x7FFFu + ((ul >> 16) & 1u)) & 0xFFFF0000u;
                g_Mbhi[d * F_DIM + f] = (uint16_t)(rh >> 16);
                g_Mblo[d * F_DIM + f] = (uint16_t)(rl >> 16);
            }
        }
    } else {
        #pragma unroll
        for (int j = 0; j < 8; j++) {
            int f = warp + j * 8;
            const float4* vrow =
                reinterpret_cast<const float4*>(V + (size_t)f * (2 * D_DIM) + D_DIM);
            float acc = 0.f;
            #pragma unroll
            for (int it = 0; it < 4; it++) {
                float4 vv = vrow[lane + it * 32];
                float4 xv = x2v[lane + it * 32];
                acc += vv.x * xv.x + vv.y * xv.y + vv.z * xv.z + vv.w * xv.w;
            }
            #pragma unroll
            for (int o = 16; o; o >>= 1) acc += __shfl_xor_sync(0xffffffffu, acc, o);
            if (lane == 0) g_c[f] = acc + b[f];
        }
    }
}

// ---------------------------------------------------------------------------
// Kernel B: HMMA (mma.sync bf16-split x3) GEMM + fused L1-norm/relu/@U.
// grid=128, 512 threads (16 warps x 16 rows). B (M) resident in smem;
// A (x1) loaded straight from global in fragment layout — no mainloop syncs.
// ---------------------------------------------------------------------------
__global__ void __launch_bounds__(NTH, 1) main_kernel(
    const float* __restrict__ x1, const float* __restrict__ U,
    float* __restrict__ out)
{
    extern __shared__ char raw[];
    char* smem = (char*)((((uintptr_t)raw) + 1023) & ~(uintptr_t)1023);
    uint32_t sb = smem_u32(smem);
    float* sc = (float*)(smem + AUX_OFF);
    float* sU = (float*)(smem + AUX_OFF + 256);

    int tid = threadIdx.x, warp = tid >> 5, lane = tid & 31;

    // prologue: cp.async B hi+lo (8192 x 16B) with XOR-16B swizzle
    {
        #pragma unroll
        for (int j = 0; j < 16; j++) {
            int i = j * NTH + tid;              // 0..8191
            int arr = i >> 12;                  // 0=hi, 1=lo
            int idx = i & 4095;
            int k = idx >> 3, nb = idx & 7;
            uint32_t dst = sb + arr * 65536 + k * 128 + ((nb * 16) ^ ((k & 7) * 16));
            const uint16_t* src = (arr ? g_Mblo : g_Mbhi) + k * F_DIM + nb * 8;
            cp_async16(dst, src);
        }
        CP_COMMIT();
    }
    if (tid < F_DIM) { sc[tid] = g_c[tid]; sU[tid] = U[tid]; }
    CP_WAIT0();
    __syncthreads();

    int g = lane >> 2, tig = lane & 3;
    int rowBase = blockIdx.x * TILE_M + warp * 16;
    const float* ap = x1 + (size_t)(rowBase + g) * D_DIM + tig * 2;
    // frag element offsets: a0:(g,c0) a1:(g+8,c0) a2:(g,c0+8) a3:(g+8,c0+8)
    const size_t aoff[4] = {0, 8 * (size_t)D_DIM, 8, 8 * (size_t)D_DIM + 8};

    // per-lane ldmatrix addrs: k-lane row + per-p column (constant across ks)
    int klane = lane & 15, nsel = lane >> 4;
    uint32_t rowoff = (uint32_t)(klane * 128);
    uint32_t colp[4];
    #pragma unroll
    for (int p = 0; p < 4; p++)
        colp[p] = (uint32_t)(((2 * p + nsel) * 16) ^ ((klane & 7) * 16));

    float acc[8][4];
    #pragma unroll
    for (int nt = 0; nt < 8; nt++)
        #pragma unroll
        for (int q = 0; q < 4; q++) acc[nt][q] = 0.f;

    // prefetch A frags for ks=0
    float2 an[4];
    #pragma unroll
    for (int j = 0; j < 4; j++)
        an[j] = *reinterpret_cast<const float2*>(ap + aoff[j]);

    #pragma unroll 4
    for (int ks = 0; ks < NKS; ks++) {
        float2 ac[4];
        #pragma unroll
        for (int j = 0; j < 4; j++) ac[j] = an[j];
        if (ks + 1 < NKS) {
            const float* apn = ap + (ks + 1) * 16;
            #pragma unroll
            for (int j = 0; j < 4; j++)
                an[j] = *reinterpret_cast<const float2*>(apn + aoff[j]);
        }

        // split A to bf16 hi/lo frags
        uint32_t Ah[4], Al[4];
        #pragma unroll
        for (int j = 0; j < 4; j++) split2(ac[j], Ah[j], Al[j]);

        uint32_t kb = ks * 2048 + rowoff;
        uint32_t bhi_base = sb + BHI_OFF + kb;
        uint32_t blo_base = sb + BLO_OFF + kb;

        #pragma unroll
        for (int p = 0; p < 4; p++) {
            uint32_t h0, h1, h2, h3, l0, l1, l2, l3;
            LDMX4T(h0, h1, h2, h3, bhi_base + colp[p]);
            LDMX4T(l0, l1, l2, l3, blo_base + colp[p]);
            // n-tiles 2p (regs 0,1) and 2p+1 (regs 2,3)
            MMA16816(acc[2 * p],     Ah[0], Ah[1], Ah[2], Ah[3], h0, h1);
            MMA16816(acc[2 * p],     Al[0], Al[1], Al[2], Al[3], h0, h1);
            MMA16816(acc[2 * p],     Ah[0], Ah[1], Ah[2], Ah[3], l0, l1);
            MMA16816(acc[2 * p + 1], Ah[0], Ah[1], Ah[2], Ah[3], h2, h3);
            MMA16816(acc[2 * p + 1], Al[0], Al[1], Al[2], Al[3], h2, h3);
            MMA16816(acc[2 * p + 1], Ah[0], Ah[1], Ah[2], Ah[3], l2, l3);
        }
    }

    // epilogue: rows g and g+8; 4 tig-lanes hold the 64 f values of each row
    #pragma unroll
    for (int h = 0; h < 2; h++) {
        float s = 0.f, num = 0.f;
        #pragma unroll
        for (int nt = 0; nt < 8; nt++) {
            int f0 = nt * 8 + tig * 2;
            float v0 = acc[nt][2 * h]     + sc[f0];
            float v1 = acc[nt][2 * h + 1] + sc[f0 + 1];
            s   += fabsf(v0) + fabsf(v1);
            num += fmaxf(v0, 0.f) * sU[f0] + fmaxf(v1, 0.f) * sU[f0 + 1];
        }
        s   += __shfl_xor_sync(0xffffffffu, s, 1);
        s   += __shfl_xor_sync(0xffffffffu, s, 2);
        num += __shfl_xor_sync(0xffffffffu, num, 1);
        num += __shfl_xor_sync(0xffffffffu, num, 2);
        if (tig == 0)
            out[rowBase + g + 8 * h] = num / fmaxf(s, 1e-12f);
    }
}

// ---------------------------------------------------------------------------
// launch
// ---------------------------------------------------------------------------
extern "C" void kernel_launch(void* const* d_in, const int* in_sizes, int n_in,
                              void* d_out, int out_size)
{
    const float* x1 = (const float*)d_in[0];   // (N, 512)
    const float* x2 = (const float*)d_in[1];   // (1, 512)
    const float* V  = (const float*)d_in[2];   // (64, 1024)
    const float* W  = (const float*)d_in[3];   // (64, 512, 512)
    const float* b  = (const float*)d_in[4];   // (64,)
    const float* U  = (const float*)d_in[5];   // (64, 1)
    float* out = (float*)d_out;                // (N, 1)

    int N = in_sizes[0] / D_DIM;               // 32768

    cudaFuncSetAttribute(main_kernel, cudaFuncAttributeMaxDynamicSharedMemorySize,
                         SMEM_BYTES + 1024);

    prep_kernel<<<1024 + 1, 256>>>(x2, V, W, b);
    main_kernel<<<N / TILE_M, NTH, SMEM_BYTES + 1024>>>(x1, U, out);
}

// round 6
// speedup vs baseline: 3.8216x; 1.0658x over previous
#include <cuda_runtime.h>
#include <cuda_bf16.h>
#include <cstdint>

// Problem constants (fixed by setup_inputs: N=32768, D=512, F=64)
#define D_DIM  512
#define F_DIM  64
#define TILE_M 256          // rows per CTA (8 warps x 32 rows)
#define NTH    256
#define NKS    (D_DIM / 16) // 32 k-steps

// SMEM: B_hi [512k][64f] bf16 swizzled (64KB) | B_lo (64KB) | sc[64] | sU[64]
#define BHI_OFF 0
#define BLO_OFF 65536
#define AUX_OFF 131072
#define SMEM_BYTES (131072 + 512 + 1024)

// Scratch (device globals: allocation-free rule)
__device__ uint16_t g_Mbhi[D_DIM * F_DIM];  // bf16 hi of M[k][f]
__device__ uint16_t g_Mblo[D_DIM * F_DIM];  // bf16 lo
__device__ float    g_c[F_DIM];             // c[f] = V2[f]·x2 + b[f]

// ---------------------------------------------------------------------------
// helpers
// ---------------------------------------------------------------------------
__device__ __forceinline__ unsigned smem_u32(const void* p) {
    return (unsigned)__cvta_generic_to_shared(p);
}
__device__ __forceinline__ void cp_async16(unsigned saddr, const void* g) {
    asm volatile("cp.async.cg.shared.global [%0], [%1], 16;\n" :: "r"(saddr), "l"(g));
}
#define CP_COMMIT() asm volatile("cp.async.commit_group;\n")
#define CP_WAIT0()  asm volatile("cp.async.wait_group 0;\n")

// float2 -> packed bf16x2 hi (RNE) + packed bf16x2 lo (residual)
__device__ __forceinline__ void split2(float2 e, uint32_t& hp, uint32_t& lp) {
    uint32_t u0 = __float_as_uint(e.x), u1 = __float_as_uint(e.y);
    uint32_t r0 = (u0 + 0x7FFFu + ((u0 >> 16) & 1u)) & 0xFFFF0000u;
    uint32_t r1 = (u1 + 0x7FFFu + ((u1 >> 16) & 1u)) & 0xFFFF0000u;
    hp = __byte_perm(r0, r1, 0x7632);           // lo16 = e.x_hi, hi16 = e.y_hi
    float l0 = e.x - __uint_as_float(r0);
    float l1 = e.y - __uint_as_float(r1);
    asm("cvt.rn.bf16x2.f32 %0, %1, %2;" : "=r"(lp) : "f"(l1), "f"(l0));
}

#define LDMX4T(r0, r1, r2, r3, a) \
    asm volatile("ldmatrix.sync.aligned.m8n8.x4.trans.shared.b16 {%0,%1,%2,%3}, [%4];" \
                 : "=r"(r0), "=r"(r1), "=r"(r2), "=r"(r3) : "r"(a))

#define MMA16816(d, a0, a1, a2, a3, b0, b1) \
    asm volatile("mma.sync.aligned.m16n8k16.row.col.f32.bf16.bf16.f32 " \
                 "{%0,%1,%2,%3}, {%4,%5,%6,%7}, {%8,%9}, {%0,%1,%2,%3};" \
                 : "+f"((d)[0]), "+f"((d)[1]), "+f"((d)[2]), "+f"((d)[3]) \
                 : "r"(a0), "r"(a1), "r"(a2), "r"(a3), "r"(b0), "r"(b1))

// ---------------------------------------------------------------------------
// Kernel A: stream W once -> M[k][f] split to bf16 hi/lo in global; also c[f]
// Each warp: 4 consecutive (f,d) rows of W, MLP=16 LDG.128 (streaming loads).
// ---------------------------------------------------------------------------
__global__ void __launch_bounds__(256) prep_kernel(
    const float* __restrict__ x2, const float* __restrict__ V,
    const float* __restrict__ W, const float* __restrict__ b)
{
    __shared__ float s_x2[D_DIM];
    int tid = threadIdx.x;
    for (int i = tid; i < D_DIM; i += blockDim.x) s_x2[i] = x2[i];
    __syncthreads();

    int lane = tid & 31;
    int warp = tid >> 5;
    const float4* x2v = reinterpret_cast<const float4*>(s_x2);

    if (blockIdx.x < 1024) {
        int r0 = blockIdx.x * 32 + warp * 4;   // rows r0..r0+3 of 32768

        float4 wv[4][4];
        #pragma unroll
        for (int r = 0; r < 4; r++) {
            const float4* wr =
                reinterpret_cast<const float4*>(W + (size_t)(r0 + r) * D_DIM);
            #pragma unroll
            for (int it = 0; it < 4; it++) wv[r][it] = __ldcs(&wr[lane + it * 32]);
        }

        float a[4] = {0.f, 0.f, 0.f, 0.f};
        #pragma unroll
        for (int it = 0; it < 4; it++) {
            float4 xv = x2v[lane + it * 32];
            #pragma unroll
            for (int r = 0; r < 4; r++) {
                a[r] += wv[r][it].x * xv.x + wv[r][it].y * xv.y
                      + wv[r][it].z * xv.z + wv[r][it].w * xv.w;
            }
        }
        #pragma unroll
        for (int o = 16; o; o >>= 1) {
            #pragma unroll
            for (int r = 0; r < 4; r++)
                a[r] += __shfl_xor_sync(0xffffffffu, a[r], o);
        }
        if (lane == 0) {
            #pragma unroll
            for (int r = 0; r < 4; r++) {
                int rr = r0 + r;
                int f = rr >> 9, d = rr & 511;
                float v = a[r] + V[(size_t)f * (2 * D_DIM) + d];
                uint32_t u = __float_as_uint(v);
                uint32_t rh = (u + 0x7FFFu + ((u >> 16) & 1u)) & 0xFFFF0000u;
                float lo = v - __uint_as_float(rh);
                uint32_t ul = __float_as_uint(lo);
                uint32_t rl = (ul + 0x7FFFu + ((ul >> 16) & 1u)) & 0xFFFF0000u;
                g_Mbhi[d * F_DIM + f] = (uint16_t)(rh >> 16);
                g_Mblo[d * F_DIM + f] = (uint16_t)(rl >> 16);
            }
        }
    } else {
        #pragma unroll
        for (int j = 0; j < 8; j++) {
            int f = warp + j * 8;
            const float4* vrow =
                reinterpret_cast<const float4*>(V + (size_t)f * (2 * D_DIM) + D_DIM);
            float acc = 0.f;
            #pragma unroll
            for (int it = 0; it < 4; it++) {
                float4 vv = vrow[lane + it * 32];
                float4 xv = x2v[lane + it * 32];
                acc += vv.x * xv.x + vv.y * xv.y + vv.z * xv.z + vv.w * xv.w;
            }
            #pragma unroll
            for (int o = 16; o; o >>= 1) acc += __shfl_xor_sync(0xffffffffu, acc, o);
            if (lane == 0) g_c[f] = acc + b[f];
        }
    }
}

// ---------------------------------------------------------------------------
// Kernel B: HMMA (mma.sync bf16-split x3) GEMM + fused L1-norm/relu/@U.
// grid=128, 256 threads (8 warps x 32 rows). B (M) resident in smem;
// A (x1) loaded straight from global in fragment layout, depth-2 prefetch.
// ---------------------------------------------------------------------------
__global__ void __launch_bounds__(NTH, 1) main_kernel(
    const float* __restrict__ x1, const float* __restrict__ U,
    float* __restrict__ out)
{
    extern __shared__ char raw[];
    char* smem = (char*)((((uintptr_t)raw) + 1023) & ~(uintptr_t)1023);
    uint32_t sb = smem_u32(smem);
    float* sc = (float*)(smem + AUX_OFF);
    float* sU = (float*)(smem + AUX_OFF + 256);

    int tid = threadIdx.x, warp = tid >> 5, lane = tid & 31;

    // prologue: cp.async B hi+lo (8192 x 16B) with XOR-16B swizzle
    {
        #pragma unroll
        for (int j = 0; j < 32; j++) {
            int i = j * NTH + tid;              // 0..8191
            int arr = i >> 12;                  // 0=hi, 1=lo
            int idx = i & 4095;
            int k = idx >> 3, nb = idx & 7;
            uint32_t dst = sb + arr * 65536 + k * 128 + ((nb * 16) ^ ((k & 7) * 16));
            const uint16_t* src = (arr ? g_Mblo : g_Mbhi) + k * F_DIM + nb * 8;
            cp_async16(dst, src);
        }
        CP_COMMIT();
    }
    if (tid < F_DIM) { sc[tid] = g_c[tid]; sU[tid] = U[tid]; }
    CP_WAIT0();
    __syncthreads();

    int g = lane >> 2, tig = lane & 3;
    int rowBase = blockIdx.x * TILE_M + warp * 32;
    const float* ap = x1 + (size_t)(rowBase + g) * D_DIM + tig * 2;
    // frag element offsets within a 16-row group:
    // a0:(g,c0) a1:(g+8,c0) a2:(g,c0+8) a3:(g+8,c0+8); rg1 adds 16 rows
    const size_t aoff[4] = {0, 8 * (size_t)D_DIM, 8, 8 * (size_t)D_DIM + 8};

    // per-lane ldmatrix addrs
    int klane = lane & 15, nsel = lane >> 4;
    uint32_t rowoff = (uint32_t)(klane * 128);
    uint32_t colp[4];
    #pragma unroll
    for (int p = 0; p < 4; p++)
        colp[p] = (uint32_t)(((2 * p + nsel) * 16) ^ ((klane & 7) * 16));

    float acc[2][8][4];
    #pragma unroll
    for (int rg = 0; rg < 2; rg++)
        #pragma unroll
        for (int nt = 0; nt < 8; nt++)
            #pragma unroll
            for (int q = 0; q < 4; q++) acc[rg][nt][q] = 0.f;

    // depth-2 prefetch of A frags
    float2 aq[2][2][4];   // [slot][rg][frag]
    #pragma unroll
    for (int s = 0; s < 2; s++)
        #pragma unroll
        for (int rg = 0; rg < 2; rg++)
            #pragma unroll
            for (int j = 0; j < 4; j++)
                aq[s][rg][j] = *reinterpret_cast<const float2*>(
                    ap + s * 16 + rg * 16 * D_DIM + aoff[j]);

    #pragma unroll 2
    for (int ks = 0; ks < NKS; ks++) {
        int slot = ks & 1;
        float2 ac[2][4];
        #pragma unroll
        for (int rg = 0; rg < 2; rg++)
            #pragma unroll
            for (int j = 0; j < 4; j++) ac[rg][j] = aq[slot][rg][j];

        if (ks + 2 < NKS) {
            const float* apn = ap + (ks + 2) * 16;
            #pragma unroll
            for (int rg = 0; rg < 2; rg++)
                #pragma unroll
                for (int j = 0; j < 4; j++)
                    aq[slot][rg][j] = *reinterpret_cast<const float2*>(
                        apn + rg * 16 * D_DIM + aoff[j]);
        }

        // split A to bf16 hi/lo frags
        uint32_t Ah[2][4], Al[2][4];
        #pragma unroll
        for (int rg = 0; rg < 2; rg++)
            #pragma unroll
            for (int j = 0; j < 4; j++) split2(ac[rg][j], Ah[rg][j], Al[rg][j]);

        uint32_t kb = ks * 2048 + rowoff;
        uint32_t bhi_base = sb + BHI_OFF + kb;
        uint32_t blo_base = sb + BLO_OFF + kb;

        #pragma unroll
        for (int p = 0; p < 4; p++) {
            uint32_t h0, h1, h2, h3, l0, l1, l2, l3;
            LDMX4T(h0, h1, h2, h3, bhi_base + colp[p]);
            LDMX4T(l0, l1, l2, l3, blo_base + colp[p]);
            #pragma unroll
            for (int rg = 0; rg < 2; rg++) {
                MMA16816(acc[rg][2 * p],     Ah[rg][0], Ah[rg][1], Ah[rg][2], Ah[rg][3], h0, h1);
                MMA16816(acc[rg][2 * p],     Al[rg][0], Al[rg][1], Al[rg][2], Al[rg][3], h0, h1);
                MMA16816(acc[rg][2 * p],     Ah[rg][0], Ah[rg][1], Ah[rg][2], Ah[rg][3], l0, l1);
                MMA16816(acc[rg][2 * p + 1], Ah[rg][0], Ah[rg][1], Ah[rg][2], Ah[rg][3], h2, h3);
                MMA16816(acc[rg][2 * p + 1], Al[rg][0], Al[rg][1], Al[rg][2], Al[rg][3], h2, h3);
                MMA16816(acc[rg][2 * p + 1], Ah[rg][0], Ah[rg][1], Ah[rg][2], Ah[rg][3], l2, l3);
            }
        }
    }

    // epilogue: per row-group rg, rows g+8h; 4 tig-lanes hold the 64 f values
    #pragma unroll
    for (int rg = 0; rg < 2; rg++) {
        #pragma unroll
        for (int h = 0; h < 2; h++) {
            float s = 0.f, num = 0.f;
            #pragma unroll
            for (int nt = 0; nt < 8; nt++) {
                int f0 = nt * 8 + tig * 2;
                float v0 = acc[rg][nt][2 * h]     + sc[f0];
                float v1 = acc[rg][nt][2 * h + 1] + sc[f0 + 1];
                s   += fabsf(v0) + fabsf(v1);
                num += fmaxf(v0, 0.f) * sU[f0] + fmaxf(v1, 0.f) * sU[f0 + 1];
            }
            s   += __shfl_xor_sync(0xffffffffu, s, 1);
            s   += __shfl_xor_sync(0xffffffffu, s, 2);
            num += __shfl_xor_sync(0xffffffffu, num, 1);
            num += __shfl_xor_sync(0xffffffffu, num, 2);
            if (tig == 0)
                out[rowBase + rg * 16 + g + 8 * h] = num / fmaxf(s, 1e-12f);
        }
    }
}

// ---------------------------------------------------------------------------
// launch
// ---------------------------------------------------------------------------
extern "C" void kernel_launch(void* const* d_in, const int* in_sizes, int n_in,
                              void* d_out, int out_size)
{
    const float* x1 = (const float*)d_in[0];   // (N, 512)
    const float* x2 = (const float*)d_in[1];   // (1, 512)
    const float* V  = (const float*)d_in[2];   // (64, 1024)
    const float* W  = (const float*)d_in[3];   // (64, 512, 512)
    const float* b  = (const float*)d_in[4];   // (64,)
    const float* U  = (const float*)d_in[5];   // (64, 1)
    float* out = (float*)d_out;                // (N, 1)

    int N = in_sizes[0] / D_DIM;               // 32768

    cudaFuncSetAttribute(main_kernel, cudaFuncAttributeMaxDynamicSharedMemorySize,
                         SMEM_BYTES + 1024);

    prep_kernel<<<1024 + 1, 256>>>(x2, V, W, b);
    main_kernel<<<N / TILE_M, NTH, SMEM_BYTES + 1024>>>(x1, U, out);
}

// round 7
// speedup vs baseline: 4.6381x; 1.2137x over previous
#include <cuda_runtime.h>
#include <cuda_fp16.h>
#include <cstdint>

// Problem constants (fixed by setup_inputs: N=32768, D=512, F=64)
#define D_DIM  512
#define F_DIM  64
#define TILE_M 128          // rows per CTA (8 warps x 16 rows)
#define NTH    256
#define NKS    (D_DIM / 16) // 32 k-steps

// SMEM: M fp16 [512 k][64 f] swizzled (64KB) | sc[64] | sU[64]
#define AUX_OFF 65536
#define SMEM_BYTES (65536 + 512 + 512)

// Scratch (device globals: allocation-free rule)
__device__ uint16_t g_Mh[D_DIM * F_DIM];   // fp16 M[k][f]
__device__ float    g_c[F_DIM];            // c[f] = V2[f]·x2 + b[f]

// ---------------------------------------------------------------------------
// helpers
// ---------------------------------------------------------------------------
__device__ __forceinline__ unsigned smem_u32(const void* p) {
    return (unsigned)__cvta_generic_to_shared(p);
}
__device__ __forceinline__ void cp_async16(unsigned saddr, const void* g) {
    asm volatile("cp.async.cg.shared.global [%0], [%1], 16;\n" :: "r"(saddr), "l"(g));
}
#define CP_COMMIT() asm volatile("cp.async.commit_group;\n")
#define CP_WAIT0()  asm volatile("cp.async.wait_group 0;\n")

// float2 -> packed half2 (lo16 = e.x, hi16 = e.y)
__device__ __forceinline__ uint32_t cvt_h2(float2 e) {
    uint32_t r;
    asm("cvt.rn.f16x2.f32 %0, %1, %2;" : "=r"(r) : "f"(e.y), "f"(e.x));
    return r;
}

#define LDMX4T(r0, r1, r2, r3, a) \
    asm volatile("ldmatrix.sync.aligned.m8n8.x4.trans.shared.b16 {%0,%1,%2,%3}, [%4];" \
                 : "=r"(r0), "=r"(r1), "=r"(r2), "=r"(r3) : "r"(a))

#define MMA16816(d, a0, a1, a2, a3, b0, b1) \
    asm volatile("mma.sync.aligned.m16n8k16.row.col.f32.f16.f16.f32 " \
                 "{%0,%1,%2,%3}, {%4,%5,%6,%7}, {%8,%9}, {%0,%1,%2,%3};" \
                 : "+f"((d)[0]), "+f"((d)[1]), "+f"((d)[2]), "+f"((d)[3]) \
                 : "r"(a0), "r"(a1), "r"(a2), "r"(a3), "r"(b0), "r"(b1))

// ---------------------------------------------------------------------------
// Kernel A: stream W once -> M[k][f] fp16 in global; also c[f]
// Each warp: 4 consecutive (f,d) rows of W, MLP=16 LDG.128 streaming.
// ---------------------------------------------------------------------------
__global__ void __launch_bounds__(256) prep_kernel(
    const float* __restrict__ x2, const float* __restrict__ V,
    const float* __restrict__ W, const float* __restrict__ b)
{
    __shared__ float s_x2[D_DIM];
    int tid = threadIdx.x;
    for (int i = tid; i < D_DIM; i += blockDim.x) s_x2[i] = x2[i];
    __syncthreads();

    int lane = tid & 31;
    int warp = tid >> 5;
    const float4* x2v = reinterpret_cast<const float4*>(s_x2);

    if (blockIdx.x < 1024) {
        int r0 = blockIdx.x * 32 + warp * 4;   // rows r0..r0+3 of 32768

        float4 wv[4][4];
        #pragma unroll
        for (int r = 0; r < 4; r++) {
            const float4* wr =
                reinterpret_cast<const float4*>(W + (size_t)(r0 + r) * D_DIM);
            #pragma unroll
            for (int it = 0; it < 4; it++) wv[r][it] = __ldcs(&wr[lane + it * 32]);
        }

        float a[4] = {0.f, 0.f, 0.f, 0.f};
        #pragma unroll
        for (int it = 0; it < 4; it++) {
            float4 xv = x2v[lane + it * 32];
            #pragma unroll
            for (int r = 0; r < 4; r++) {
                a[r] += wv[r][it].x * xv.x + wv[r][it].y * xv.y
                      + wv[r][it].z * xv.z + wv[r][it].w * xv.w;
            }
        }
        #pragma unroll
        for (int o = 16; o; o >>= 1) {
            #pragma unroll
            for (int r = 0; r < 4; r++)
                a[r] += __shfl_xor_sync(0xffffffffu, a[r], o);
        }
        if (lane == 0) {
            #pragma unroll
            for (int r = 0; r < 4; r++) {
                int rr = r0 + r;
                int f = rr >> 9, d = rr & 511;
                float v = a[r] + V[(size_t)f * (2 * D_DIM) + d];
                __half hv = __float2half_rn(v);
                g_Mh[d * F_DIM + f] = *reinterpret_cast<uint16_t*>(&hv);
            }
        }
    } else {
        #pragma unroll
        for (int j = 0; j < 8; j++) {
            int f = warp + j * 8;
            const float4* vrow =
                reinterpret_cast<const float4*>(V + (size_t)f * (2 * D_DIM) + D_DIM);
            float acc = 0.f;
            #pragma unroll
            for (int it = 0; it < 4; it++) {
                float4 vv = vrow[lane + it * 32];
                float4 xv = x2v[lane + it * 32];
                acc += vv.x * xv.x + vv.y * xv.y + vv.z * xv.z + vv.w * xv.w;
            }
            #pragma unroll
            for (int o = 16; o; o >>= 1) acc += __shfl_xor_sync(0xffffffffu, acc, o);
            if (lane == 0) g_c[f] = acc + b[f];
        }
    }
}

// ---------------------------------------------------------------------------
// Kernel B: fp16 HMMA GEMM (single MMA) + fused L1-norm/relu/@U.
// grid=256, 256 threads (8 warps x 16 rows), 3 CTAs/SM.
// M resident in smem (64KB); A (x1) from global, depth-2 prefetch, no syncs.
// ---------------------------------------------------------------------------
__global__ void __launch_bounds__(NTH, 3) main_kernel(
    const float* __restrict__ x1, const float* __restrict__ U,
    float* __restrict__ out)
{
    extern __shared__ char smem[];
    uint32_t sb = smem_u32(smem);
    float* sc = (float*)(smem + AUX_OFF);
    float* sU = (float*)(smem + AUX_OFF + 256);

    int tid = threadIdx.x, warp = tid >> 5, lane = tid & 31;

    // prologue: cp.async M (4096 x 16B) with XOR-16B swizzle
    {
        #pragma unroll
        for (int j = 0; j < 16; j++) {
            int i = j * NTH + tid;              // 0..4095
            int k = i >> 3, nb = i & 7;
            uint32_t dst = sb + k * 128 + ((nb * 16) ^ ((k & 7) * 16));
            cp_async16(dst, g_Mh + k * F_DIM + nb * 8);
        }
        CP_COMMIT();
    }
    if (tid < F_DIM) { sc[tid] = g_c[tid]; sU[tid] = U[tid]; }
    CP_WAIT0();
    __syncthreads();

    int g = lane >> 2, tig = lane & 3;
    int rowBase = blockIdx.x * TILE_M + warp * 16;
    const float* ap = x1 + (size_t)(rowBase + g) * D_DIM + tig * 2;
    // frag offsets: a0:(g,c0) a1:(g+8,c0) a2:(g,c0+8) a3:(g+8,c0+8)
    const size_t aoff[4] = {0, 8 * (size_t)D_DIM, 8, 8 * (size_t)D_DIM + 8};

    // per-lane ldmatrix addrs
    int klane = lane & 15, nsel = lane >> 4;
    uint32_t rowoff = (uint32_t)(klane * 128);
    uint32_t colp[4];
    #pragma unroll
    for (int p = 0; p < 4; p++)
        colp[p] = (uint32_t)(((2 * p + nsel) * 16) ^ ((klane & 7) * 16));

    float acc[8][4];
    #pragma unroll
    for (int nt = 0; nt < 8; nt++)
        #pragma unroll
        for (int q = 0; q < 4; q++) acc[nt][q] = 0.f;

    // depth-2 prefetch of A frags
    float2 aq[2][4];
    #pragma unroll
    for (int s = 0; s < 2; s++)
        #pragma unroll
        for (int j = 0; j < 4; j++)
            aq[s][j] = *reinterpret_cast<const float2*>(ap + s * 16 + aoff[j]);

    #pragma unroll 4
    for (int ks = 0; ks < NKS; ks++) {
        int slot = ks & 1;
        uint32_t Ah[4];
        #pragma unroll
        for (int j = 0; j < 4; j++) Ah[j] = cvt_h2(aq[slot][j]);

        if (ks + 2 < NKS) {
            const float* apn = ap + (ks + 2) * 16;
            #pragma unroll
            for (int j = 0; j < 4; j++)
                aq[slot][j] = *reinterpret_cast<const float2*>(apn + aoff[j]);
        }

        uint32_t bbase = sb + ks * 2048 + rowoff;
        #pragma unroll
        for (int p = 0; p < 4; p++) {
            uint32_t h0, h1, h2, h3;
            LDMX4T(h0, h1, h2, h3, bbase + colp[p]);
            MMA16816(acc[2 * p],     Ah[0], Ah[1], Ah[2], Ah[3], h0, h1);
            MMA16816(acc[2 * p + 1], Ah[0], Ah[1], Ah[2], Ah[3], h2, h3);
        }
    }

    // epilogue: rows g and g+8; 4 tig-lanes hold the 64 f values of each row
    #pragma unroll
    for (int h = 0; h < 2; h++) {
        float s = 0.f, num = 0.f;
        #pragma unroll
        for (int nt = 0; nt < 8; nt++) {
            int f0 = nt * 8 + tig * 2;
            float v0 = acc[nt][2 * h]     + sc[f0];
            float v1 = acc[nt][2 * h + 1] + sc[f0 + 1];
            s   += fabsf(v0) + fabsf(v1);
            num += fmaxf(v0, 0.f) * sU[f0] + fmaxf(v1, 0.f) * sU[f0 + 1];
        }
        s   += __shfl_xor_sync(0xffffffffu, s, 1);
        s   += __shfl_xor_sync(0xffffffffu, s, 2);
        num += __shfl_xor_sync(0xffffffffu, num, 1);
        num += __shfl_xor_sync(0xffffffffu, num, 2);
        if (tig == 0)
            out[rowBase + g + 8 * h] = num / fmaxf(s, 1e-12f);
    }
}

// ---------------------------------------------------------------------------
// launch
// ---------------------------------------------------------------------------
extern "C" void kernel_launch(void* const* d_in, const int* in_sizes, int n_in,
                              void* d_out, int out_size)
{
    const float* x1 = (const float*)d_in[0];   // (N, 512)
    const float* x2 = (const float*)d_in[1];   // (1, 512)
    const float* V  = (const float*)d_in[2];   // (64, 1024)
    const float* W  = (const float*)d_in[3];   // (64, 512, 512)
    const float* b  = (const float*)d_in[4];   // (64,)
    const float* U  = (const float*)d_in[5];   // (64, 1)
    float* out = (float*)d_out;                // (N, 1)

    int N = in_sizes[0] / D_DIM;               // 32768

    cudaFuncSetAttribute(main_kernel, cudaFuncAttributeMaxDynamicSharedMemorySize,
                         SMEM_BYTES);

    prep_kernel<<<1024 + 1, 256>>>(x2, V, W, b);
    main_kernel<<<N / TILE_M, NTH, SMEM_BYTES>>>(x1, U, out);
}

// round 8
// speedup vs baseline: 4.9375x; 1.0645x over previous
#include <cuda_runtime.h>
#include <cuda_fp16.h>
#include <cstdint>

// Problem constants (fixed by setup_inputs: N=32768, D=512, F=64)
#define D_DIM  512
#define F_DIM  64
#define TILE_M 256          // rows per CTA (8 warps x 32 rows)
#define NTH    256
#define NSLAB  16           // 16 slabs of 32 k
#define STAGES 4

// SMEM: M fp16 [512k][64f] swizzled (64KB) | 4x A-stage (32KB) | sc | sU
#define STG_OFF 65536
#define AUX_OFF (65536 + STAGES * 32768)          // 196608
#define SMEM_BYTES (AUX_OFF + 512 + 512)

// Scratch (device globals: allocation-free rule)
__device__ uint16_t g_Mh[D_DIM * F_DIM];   // fp16 M[k][f]
__device__ float    g_c[F_DIM];            // c[f] = V2[f]·x2 + b[f]

// ---------------------------------------------------------------------------
// helpers
// ---------------------------------------------------------------------------
__device__ __forceinline__ unsigned smem_u32(const void* p) {
    return (unsigned)__cvta_generic_to_shared(p);
}
__device__ __forceinline__ void cp_async16(unsigned saddr, const void* g) {
    asm volatile("cp.async.cg.shared.global [%0], [%1], 16;\n" :: "r"(saddr), "l"(g));
}
#define CP_COMMIT() asm volatile("cp.async.commit_group;\n")
#define CP_WAIT(n)  asm volatile("cp.async.wait_group %0;\n" :: "n"(n))

// float2 -> packed half2 (lo16 = e.x, hi16 = e.y)
__device__ __forceinline__ uint32_t cvt_h2(float2 e) {
    uint32_t r;
    asm("cvt.rn.f16x2.f32 %0, %1, %2;" : "=r"(r) : "f"(e.y), "f"(e.x));
    return r;
}
__device__ __forceinline__ float2 lds64(uint32_t a) {
    float2 v;
    asm volatile("ld.shared.v2.f32 {%0, %1}, [%2];" : "=f"(v.x), "=f"(v.y) : "r"(a));
    return v;
}

#define LDMX4T(r0, r1, r2, r3, a) \
    asm volatile("ldmatrix.sync.aligned.m8n8.x4.trans.shared.b16 {%0,%1,%2,%3}, [%4];" \
                 : "=r"(r0), "=r"(r1), "=r"(r2), "=r"(r3) : "r"(a))

#define MMA16816(d, a0, a1, a2, a3, b0, b1) \
    asm volatile("mma.sync.aligned.m16n8k16.row.col.f32.f16.f16.f32 " \
                 "{%0,%1,%2,%3}, {%4,%5,%6,%7}, {%8,%9}, {%0,%1,%2,%3};" \
                 : "+f"((d)[0]), "+f"((d)[1]), "+f"((d)[2]), "+f"((d)[3]) \
                 : "r"(a0), "r"(a1), "r"(a2), "r"(a3), "r"(b0), "r"(b1))

// ---------------------------------------------------------------------------
// Kernel A: stream W once -> M[k][f] fp16 in global; also c[f]
// ---------------------------------------------------------------------------
__global__ void __launch_bounds__(256) prep_kernel(
    const float* __restrict__ x2, const float* __restrict__ V,
    const float* __restrict__ W, const float* __restrict__ b)
{
    __shared__ float s_x2[D_DIM];
    int tid = threadIdx.x;
    for (int i = tid; i < D_DIM; i += blockDim.x) s_x2[i] = x2[i];
    __syncthreads();

    int lane = tid & 31;
    int warp = tid >> 5;
    const float4* x2v = reinterpret_cast<const float4*>(s_x2);

    if (blockIdx.x < 1024) {
        int r0 = blockIdx.x * 32 + warp * 4;   // rows r0..r0+3 of 32768

        float4 wv[4][4];
        #pragma unroll
        for (int r = 0; r < 4; r++) {
            const float4* wr =
                reinterpret_cast<const float4*>(W + (size_t)(r0 + r) * D_DIM);
            #pragma unroll
            for (int it = 0; it < 4; it++) wv[r][it] = __ldcs(&wr[lane + it * 32]);
        }

        float a[4] = {0.f, 0.f, 0.f, 0.f};
        #pragma unroll
        for (int it = 0; it < 4; it++) {
            float4 xv = x2v[lane + it * 32];
            #pragma unroll
            for (int r = 0; r < 4; r++) {
                a[r] += wv[r][it].x * xv.x + wv[r][it].y * xv.y
                      + wv[r][it].z * xv.z + wv[r][it].w * xv.w;
            }
        }
        #pragma unroll
        for (int o = 16; o; o >>= 1) {
            #pragma unroll
            for (int r = 0; r < 4; r++)
                a[r] += __shfl_xor_sync(0xffffffffu, a[r], o);
        }
        if (lane == 0) {
            #pragma unroll
            for (int r = 0; r < 4; r++) {
                int rr = r0 + r;
                int f = rr >> 9, d = rr & 511;
                float v = a[r] + V[(size_t)f * (2 * D_DIM) + d];
                __half hv = __float2half_rn(v);
                g_Mh[d * F_DIM + f] = *reinterpret_cast<uint16_t*>(&hv);
            }
        }
    } else {
        #pragma unroll
        for (int j = 0; j < 8; j++) {
            int f = warp + j * 8;
            const float4* vrow =
                reinterpret_cast<const float4*>(V + (size_t)f * (2 * D_DIM) + D_DIM);
            float acc = 0.f;
            #pragma unroll
            for (int it = 0; it < 4; it++) {
                float4 vv = vrow[lane + it * 32];
                float4 xv = x2v[lane + it * 32];
                acc += vv.x * xv.x + vv.y * xv.y + vv.z * xv.z + vv.w * xv.w;
            }
            #pragma unroll
            for (int o = 16; o; o >>= 1) acc += __shfl_xor_sync(0xffffffffu, acc, o);
            if (lane == 0) g_c[f] = acc + b[f];
        }
    }
}

// ---------------------------------------------------------------------------
// Kernel B: fp16 HMMA GEMM + fused L1-norm/relu/@U, cp.async multistage x1.
// grid=128, 256 threads (8 warps x 32 rows). M resident; x1 staged 4-deep.
// ---------------------------------------------------------------------------
__global__ void __launch_bounds__(NTH) main_kernel(
    const float* __restrict__ x1, const float* __restrict__ U,
    float* __restrict__ out)
{
    extern __shared__ char smem[];
    uint32_t sb = smem_u32(smem);
    float* sc = (float*)(smem + AUX_OFF);
    float* sU = (float*)(smem + AUX_OFF + 256);

    int tid = threadIdx.x, warp = tid >> 5, lane = tid & 31;
    int base = blockIdx.x * TILE_M;

    // stage issuer: 2048 x 16B coalesced, 8 per thread, 16B-XOR swizzle
    auto issue_stage = [&](int s) {
        int buf = s & (STAGES - 1);
        const float* src = x1 + (size_t)base * D_DIM + s * 32;
        #pragma unroll
        for (int j = 0; j < 8; j++) {
            int i = j * NTH + tid;
            int row = i >> 3, c = i & 7;
            cp_async16(sb + STG_OFF + buf * 32768 + row * 128 + ((c ^ (row & 7)) * 16),
                       src + (size_t)row * D_DIM + c * 4);
        }
    };

    // prologue: M (4096 x 16B) + stage 0 in group 0; stages 1,2 in groups 1,2
    {
        #pragma unroll
        for (int j = 0; j < 16; j++) {
            int i = j * NTH + tid;              // 0..4095
            int k = i >> 3, nb = i & 7;
            uint32_t dst = sb + k * 128 + ((nb * 16) ^ ((k & 7) * 16));
            cp_async16(dst, g_Mh + k * F_DIM + nb * 8);
        }
        issue_stage(0);
        CP_COMMIT();
        issue_stage(1);
        CP_COMMIT();
        issue_stage(2);
        CP_COMMIT();
    }
    if (tid < F_DIM) { sc[tid] = g_c[tid]; sU[tid] = U[tid]; }

    int g = lane >> 2, tig = lane & 3;
    // ldmatrix B addressing
    int klane = lane & 15, nsel = lane >> 4;
    uint32_t rowoff = (uint32_t)(klane * 128);
    uint32_t colp[4];
    #pragma unroll
    for (int p = 0; p < 4; p++)
        colp[p] = (uint32_t)(((2 * p + nsel) * 16) ^ ((klane & 7) * 16));

    float acc[2][8][4];
    #pragma unroll
    for (int rg = 0; rg < 2; rg++)
        #pragma unroll
        for (int nt = 0; nt < 8; nt++)
            #pragma unroll
            for (int q = 0; q < 4; q++) acc[rg][nt][q] = 0.f;

    // A-frag LDS byte offsets (within stage buffer), per (rg, h, j)
    uint32_t aoffs[2][2][2];
    #pragma unroll
    for (int rg = 0; rg < 2; rg++)
        #pragma unroll
        for (int h = 0; h < 2; h++)
            #pragma unroll
            for (int j = 0; j < 2; j++) {
                int R = warp * 32 + rg * 16 + g + 8 * h;
                int c = j * 2 + (tig >> 1);     // + ksub*4 added in loop
                aoffs[rg][h][j] = (uint32_t)(R * 128 + (tig & 1) * 8)
                                  ^ (uint32_t)0 | 0;  // base; swizzle applied per ksub
                // store raw parts; final addr computed in loop
                aoffs[rg][h][j] = (uint32_t)((R << 7) | (c << 1) | ((tig & 1)));
            }

    for (int s = 0; s < NSLAB; s++) {
        int buf = s & (STAGES - 1);
        CP_WAIT(2);
        __syncthreads();

        uint32_t abase = sb + STG_OFF + buf * 32768;
        #pragma unroll
        for (int ksub = 0; ksub < 2; ksub++) {
            // load + convert A frags
            uint32_t Ah[2][4];
            #pragma unroll
            for (int rg = 0; rg < 2; rg++)
                #pragma unroll
                for (int h = 0; h < 2; h++)
                    #pragma unroll
                    for (int j = 0; j < 2; j++) {
                        uint32_t enc = aoffs[rg][h][j];
                        int R = enc >> 7;
                        int c = ((enc >> 1) & 0x3F) + ksub * 4;
                        int lo8 = (enc & 1) * 8;
                        uint32_t addr = abase + (R << 7)
                                      + (uint32_t)(((c ^ (R & 7)) * 16) + lo8);
                        Ah[rg][h + 2 * j] = cvt_h2(lds64(addr));
                    }

            uint32_t bbase = sb + (uint32_t)((s * 32 + ksub * 16) * 128) + rowoff;
            #pragma unroll
            for (int p = 0; p < 4; p++) {
                uint32_t h0, h1, h2, h3;
                LDMX4T(h0, h1, h2, h3, bbase + colp[p]);
                #pragma unroll
                for (int rg = 0; rg < 2; rg++) {
                    MMA16816(acc[rg][2 * p],     Ah[rg][0], Ah[rg][1], Ah[rg][2], Ah[rg][3], h0, h1);
                    MMA16816(acc[rg][2 * p + 1], Ah[rg][0], Ah[rg][1], Ah[rg][2], Ah[rg][3], h2, h3);
                }
            }
        }

        if (s + 3 < NSLAB) issue_stage(s + 3);
        CP_COMMIT();
    }

    // epilogue: per row-group rg, rows g+8h; 4 tig-lanes hold the 64 f values
    int rowBase = base + warp * 32;
    #pragma unroll
    for (int rg = 0; rg < 2; rg++) {
        #pragma unroll
        for (int h = 0; h < 2; h++) {
            float s = 0.f, num = 0.f;
            #pragma unroll
            for (int nt = 0; nt < 8; nt++) {
                int f0 = nt * 8 + tig * 2;
                float v0 = acc[rg][nt][2 * h]     + sc[f0];
                float v1 = acc[rg][nt][2 * h + 1] + sc[f0 + 1];
                s   += fabsf(v0) + fabsf(v1);
                num += fmaxf(v0, 0.f) * sU[f0] + fmaxf(v1, 0.f) * sU[f0 + 1];
            }
            s   += __shfl_xor_sync(0xffffffffu, s, 1);
            s   += __shfl_xor_sync(0xffffffffu, s, 2);
            num += __shfl_xor_sync(0xffffffffu, num, 1);
            num += __shfl_xor_sync(0xffffffffu, num, 2);
            if (tig == 0)
                out[rowBase + rg * 16 + g + 8 * h] = num / fmaxf(s, 1e-12f);
        }
    }
}

// ---------------------------------------------------------------------------
// launch
// ---------------------------------------------------------------------------
extern "C" void kernel_launch(void* const* d_in, const int* in_sizes, int n_in,
                              void* d_out, int out_size)
{
    const float* x1 = (const float*)d_in[0];   // (N, 512)
    const float* x2 = (const float*)d_in[1];   // (1, 512)
    const float* V  = (const float*)d_in[2];   // (64, 1024)
    const float* W  = (const float*)d_in[3];   // (64, 512, 512)
    const float* b  = (const float*)d_in[4];   // (64,)
    const float* U  = (const float*)d_in[5];   // (64, 1)
    float* out = (float*)d_out;                // (N, 1)

    int N = in_sizes[0] / D_DIM;               // 32768

    cudaFuncSetAttribute(main_kernel, cudaFuncAttributeMaxDynamicSharedMemorySize,
                         SMEM_BYTES);

    prep_kernel<<<1024 + 1, 256>>>(x2, V, W, b);
    main_kernel<<<N / TILE_M, NTH, SMEM_BYTES>>>(x1, U, out);
}